// round 13
// baseline (speedup 1.0000x reference)
#include <cuda_runtime.h>
#include <cuda_bf16.h>
#include <cstdint>
#include <cmath>

// Problem constants: B=4, S=4096, E=1024, H=16, hd=64
#define TOK     16384            // B*S
#define EDIM    1024
#define NHEAD   16
#define HDIM    64
#define BH      64               // B*H
#define SEQ     4096
#define EPSN    1e-4f
#define NCHUNK  32               // s-chunks for partial scores

// ---------------- scratch (static device memory; no allocations) -----------
__device__ float g_wn[4u * 1024u * 1024u];                 // concat wq|wk|wv|wo (tf32)
__device__ float g_qkv[3u * (size_t)TOK * EDIM];           // q | k | v outputs
__device__ float g_o[(size_t)TOK * EDIM];                  // attn output
__device__ float g_scp[(size_t)NCHUNK * BH * HDIM * HDIM]; // partial scores (32 MB)
__device__ float g_attn[BH * HDIM * HDIM];                 // softmaxed attn

// ======================= PTX helpers ========================================
__device__ __forceinline__ uint32_t smem_to_u32(const void* p) {
    uint32_t a;
    asm("{ .reg .u64 t; cvta.to.shared.u64 t, %1; cvt.u32.u64 %0, t; }" : "=r"(a) : "l"(p));
    return a;
}
__device__ __forceinline__ float to_tf32(float x) {
    float r;
    asm("cvt.rna.tf32.f32 %0, %1;" : "=f"(r) : "f"(x));
    return r;
}

#define CP_ASYNC16(dst, src) \
    asm volatile("cp.async.cg.shared.global [%0], [%1], 16;" :: "r"(dst), "l"(src))
#define CP_COMMIT()  asm volatile("cp.async.commit_group;" ::: "memory")
#define CP_WAIT1()   asm volatile("cp.async.wait_group 1;" ::: "memory")

// m16n8k8 tf32 MMA (arch-portable; lowers to fallback HMMA on sm_103)
__device__ __forceinline__ void mma_tf32(float* d, const uint32_t* a, const uint32_t* b) {
    asm volatile(
        "mma.sync.aligned.m16n8k8.row.col.f32.tf32.tf32.f32 "
        "{%0,%1,%2,%3}, {%4,%5,%6,%7}, {%8,%9}, {%0,%1,%2,%3};"
        : "+f"(d[0]), "+f"(d[1]), "+f"(d[2]), "+f"(d[3])
        : "r"(a[0]), "r"(a[1]), "r"(a[2]), "r"(a[3]), "r"(b[0]), "r"(b[1]));
}

// ldmatrix x4: four 8x8-b16 matrices == four 8x4-tf32 fragments
__device__ __forceinline__ void ldsm_x4(uint32_t& r0, uint32_t& r1, uint32_t& r2,
                                        uint32_t& r3, uint32_t addr) {
    asm volatile("ldmatrix.sync.aligned.m8n8.x4.shared.b16 {%0,%1,%2,%3}, [%4];"
                 : "=r"(r0), "=r"(r1), "=r"(r2), "=r"(r3) : "r"(addr));
}

// ======================= tf32 mma.sync GEMM =================================
// C[row, col_global] = sum_k A[row,k] * B[col_global,k]
// QKV fused: grid.x=12 routes 256-col tiles to q|k|v thirds; out: grid.x=4.
// CTA tile 128(M) x 256(N), 512 threads = 16 warps (2Mx8N, warp tile 64x32).
// K-chunk 32, 3-stage cp.async, one barrier per chunk. 1 CTA/SM, 16 warps/SM.
#define PADW    36                       // floats per smem row (32 + 4 pad)
#define ASTAGEF (128 * PADW)             // A floats per stage
#define BSTAGEF (256 * PADW)             // B floats per stage
#define GEMM_SMEM_BYTES ((3 * ASTAGEF + 3 * BSTAGEF) * 4)   // 165888

__global__ __launch_bounds__(512, 1)
void gemm_tc_kernel(const float* __restrict__ A, const float* __restrict__ B,
                    float* __restrict__ C, const float* __restrict__ Res, float alpha)
{
    extern __shared__ __align__(16) float smem[];
    float* sA0 = smem;                   // 3 stages of A
    float* sB0 = smem + 3 * ASTAGEF;     // 3 stages of B
    const uint32_t sbaseA = smem_to_u32(sA0);
    const uint32_t sbaseB = smem_to_u32(sB0);

    const int tid = threadIdx.x;
    const int wid = tid >> 5;
    const int lane = tid & 31;
    const int g = lane >> 2;            // group id 0..7
    const int tig = lane & 3;           // thread-in-group 0..3
    const int m0 = (wid >> 3) * 64;     // warp M offset (2 M-warps)
    const int n0 = (wid & 7) * 32;      // warp N offset (8 N-warps)
    const int bm = blockIdx.y * 128;
    const int bn = blockIdx.x * 256;    // global col base (may exceed 1024 in QKV mode)

    const int mat = bn >> 10;
    const int bnl = bn & 1023;          // col base within the output matrix
    float* Cbase = C + (size_t)mat * ((size_t)TOK * EDIM);

    const int q = lane >> 3, r = lane & 7;
    const int laneA = ((q & 1) * 8 + r) * PADW + (q >> 1) * 4;
    const int laneB = ((q >> 1) * 8 + r) * PADW + (q & 1) * 4;

    const char* gA = (const char*)(A + (size_t)bm * EDIM);
    const char* gB = (const char*)(B + (size_t)bn * EDIM);

    // loader: one K-chunk (A: 128 rows, B: 256 rows; 32 floats) into stage st
    auto load_chunk = [&](int kc, int st) {
        uint32_t dA = sbaseA + (uint32_t)st * (ASTAGEF * 4);
        uint32_t dB = sbaseB + (uint32_t)st * (BSTAGEF * 4);
        int koff = kc * 128;                 // byte offset of chunk within row
        #pragma unroll
        for (int rr = 0; rr < 2; rr++) {     // A: 1024 float4 slots
            int f = tid + rr * 512;
            int row = f >> 3;                // 0..127
            int seg = (f & 7) * 16;
            CP_ASYNC16(dA + (uint32_t)(row * (PADW * 4) + seg),
                       gA + (size_t)row * (EDIM * 4) + koff + seg);
        }
        #pragma unroll
        for (int rr = 0; rr < 4; rr++) {     // B: 2048 float4 slots
            int f = tid + rr * 512;
            int row = f >> 3;                // 0..255
            int seg = (f & 7) * 16;
            CP_ASYNC16(dB + (uint32_t)(row * (PADW * 4) + seg),
                       gB + (size_t)row * (EDIM * 4) + koff + seg);
        }
    };

    float acc[4][4][4];
    #pragma unroll
    for (int i = 0; i < 4; i++)
        #pragma unroll
        for (int j = 0; j < 4; j++)
            #pragma unroll
            for (int c = 0; c < 4; c++) acc[i][j][c] = 0.f;

    load_chunk(0, 0); CP_COMMIT();
    load_chunk(1, 1); CP_COMMIT();

    for (int c = 0; c < 32; c++) {
        CP_WAIT1();
        __syncthreads();   // chunk c visible; all warps done reading stage (c-1)%3

        if (c + 2 < 32) load_chunk(c + 2, (c + 2) % 3);
        CP_COMMIT();                      // always commit (possibly empty group)

        const uint32_t stA = sbaseA + (uint32_t)(c % 3) * (ASTAGEF * 4);
        const uint32_t stB = sbaseB + (uint32_t)(c % 3) * (BSTAGEF * 4);
        const uint32_t aBase = stA + (uint32_t)((m0 * PADW + laneA) * 4);
        const uint32_t bBase = stB + (uint32_t)((n0 * PADW + laneB) * 4);

        #pragma unroll
        for (int ks = 0; ks < 4; ks++) {
            uint32_t a[4][4];
            #pragma unroll
            for (int i = 0; i < 4; i++)
                ldsm_x4(a[i][0], a[i][1], a[i][2], a[i][3],
                        aBase + (uint32_t)(i * (16 * PADW * 4) + ks * 32));
            uint32_t b[4][2];
            #pragma unroll
            for (int jp = 0; jp < 2; jp++)
                ldsm_x4(b[jp * 2][0], b[jp * 2][1], b[jp * 2 + 1][0], b[jp * 2 + 1][1],
                        bBase + (uint32_t)(jp * (16 * PADW * 4) + ks * 32));
            #pragma unroll
            for (int i = 0; i < 4; i++)
                #pragma unroll
                for (int j = 0; j < 4; j++)
                    mma_tf32(acc[i][j], a[i], b[j]);
        }
    }

    #pragma unroll
    for (int i = 0; i < 4; i++) {
        int row = bm + m0 + 16 * i + g;
        #pragma unroll
        for (int j = 0; j < 4; j++) {
            int col = bnl + n0 + 8 * j + tig * 2;
            float2 v0 = make_float2(acc[i][j][0], acc[i][j][1]);
            float2 v1 = make_float2(acc[i][j][2], acc[i][j][3]);
            if (Res != nullptr) {
                float2 r0 = *(const float2*)(Res + (size_t)row * EDIM + col);
                float2 r1 = *(const float2*)(Res + (size_t)(row + 8) * EDIM + col);
                v0.x = (v0.x + r0.x) * alpha; v0.y = (v0.y + r0.y) * alpha;
                v1.x = (v1.x + r1.x) * alpha; v1.y = (v1.y + r1.y) * alpha;
            }
            *(float2*)(Cbase + (size_t)row * EDIM + col) = v0;
            *(float2*)(Cbase + (size_t)(row + 8) * EDIM + col) = v1;
        }
    }
}

// ---------------- magnitude-preserving weight normalization (-> tf32) ------
__global__ __launch_bounds__(256)
void norm_weights_kernel(const float* __restrict__ wq, const float* __restrict__ wk,
                         const float* __restrict__ wv, const float* __restrict__ wo,
                         const float* __restrict__ gain_p)
{
    int row = blockIdx.x;
    int mat = blockIdx.y;
    const float* W = (mat == 0) ? wq : (mat == 1) ? wk : (mat == 2) ? wv : wo;
    const float* src = W + (size_t)row * EDIM;

    int tid = threadIdx.x;
    float4 w4 = *(const float4*)(src + tid * 4);
    float ss = w4.x * w4.x + w4.y * w4.y + w4.z * w4.z + w4.w * w4.w;

    __shared__ float red[8];
    int lane = tid & 31, warp = tid >> 5;
    #pragma unroll
    for (int o = 16; o > 0; o >>= 1) ss += __shfl_xor_sync(0xffffffffu, ss, o);
    if (lane == 0) red[warp] = ss;
    __syncthreads();
    if (tid == 0) {
        float t = 0.f;
        #pragma unroll
        for (int i = 0; i < 8; i++) t += red[i];
        red[0] = t;
    }
    __syncthreads();
    float scale = (*gain_p * (1.0f / 32.0f)) / (EPSN + sqrtf(red[0]) * (1.0f / 32.0f));

    float* dst = g_wn + (size_t)mat * (1024u * 1024u) + (size_t)row * EDIM + tid * 4;
    *(float4*)dst = make_float4(to_tf32(w4.x * scale), to_tf32(w4.y * scale),
                                to_tf32(w4.z * scale), to_tf32(w4.w * scale));
}

// ---------------- partial scores on tensor cores (+ fused q/k head-norm) ---
#define SPAD 36
__global__ __launch_bounds__(256)
void scores_part_tc_kernel()
{
    int bn = blockIdx.x;      // 0..63
    int chunk = blockIdx.y;   // 0..NCHUNK-1
    int b = bn >> 4, n = bn & 15;

    __shared__ __align__(16) float stq[64 * SPAD];   // q^T: [h][s], s-tile of 32
    __shared__ __align__(16) float stk[64 * SPAD];   // k^T: [k][s]

    const float* gq = g_qkv;
    const float* gk = g_qkv + (size_t)TOK * EDIM;

    int tid = threadIdx.x, wid = tid >> 5, lane = tid & 31;
    int g = lane >> 2, tig = lane & 3;

    int m0 = (wid & 3) * 16;
    int n0 = (wid >> 2) * 32;

    float acc[4][4];
    #pragma unroll
    for (int j = 0; j < 4; j++)
        #pragma unroll
        for (int c = 0; c < 4; c++) acc[j][c] = 0.f;

    const int CSZ = SEQ / NCHUNK;   // 128
    size_t tokbase = (size_t)b * SEQ + (size_t)chunk * CSZ;

    for (int s0 = 0; s0 < CSZ; s0 += 32) {
        #pragma unroll
        for (int rr = 0; rr < 4; rr++) {
            int srow = wid * 4 + rr;
            size_t goff = (tokbase + s0 + srow) * EDIM + (size_t)n * HDIM;
            float qa = gq[goff + lane], qb = gq[goff + 32 + lane];
            float ka = gk[goff + lane], kb = gk[goff + 32 + lane];
            float sq = qa * qa + qb * qb;
            float sk = ka * ka + kb * kb;
            #pragma unroll
            for (int o = 16; o > 0; o >>= 1) {
                sq += __shfl_xor_sync(0xffffffffu, sq, o);
                sk += __shfl_xor_sync(0xffffffffu, sk, o);
            }
            float iq = 1.0f / (EPSN + sqrtf(sq) * 0.125f);
            float ik = 1.0f / (EPSN + sqrtf(sk) * 0.125f);
            stq[lane * SPAD + srow]        = to_tf32(qa * iq);
            stq[(lane + 32) * SPAD + srow] = to_tf32(qb * iq);
            stk[lane * SPAD + srow]        = to_tf32(ka * ik);
            stk[(lane + 32) * SPAD + srow] = to_tf32(kb * ik);
        }
        __syncthreads();

        #pragma unroll
        for (int ks = 0; ks < 4; ks++) {
            int kc = ks * 8 + tig;
            uint32_t a[4];
            a[0] = __float_as_uint(stq[(m0 + g) * SPAD + kc]);
            a[1] = __float_as_uint(stq[(m0 + g + 8) * SPAD + kc]);
            a[2] = __float_as_uint(stq[(m0 + g) * SPAD + kc + 4]);
            a[3] = __float_as_uint(stq[(m0 + g + 8) * SPAD + kc + 4]);
            #pragma unroll
            for (int j = 0; j < 4; j++) {
                uint32_t bf[2];
                bf[0] = __float_as_uint(stk[(n0 + 8 * j + g) * SPAD + kc]);
                bf[1] = __float_as_uint(stk[(n0 + 8 * j + g) * SPAD + kc + 4]);
                mma_tf32(acc[j], a, bf);
            }
        }
        __syncthreads();
    }

    size_t base = ((size_t)chunk * BH + bn) * (HDIM * HDIM);
    #pragma unroll
    for (int j = 0; j < 4; j++) {
        int kcol = n0 + 8 * j + tig * 2;
        *(float2*)&g_scp[base + (size_t)(m0 + g) * HDIM + kcol] =
            make_float2(acc[j][0], acc[j][1]);
        *(float2*)&g_scp[base + (size_t)(m0 + g + 8) * HDIM + kcol] =
            make_float2(acc[j][2], acc[j][3]);
    }
}

// ---------------- softmax over k (rows of length 64) ------------------------
__global__ __launch_bounds__(256)
void softmax_kernel()
{
    int gw = blockIdx.x * 8 + (threadIdx.x >> 5);
    int lane = threadIdx.x & 31;
    int bn = gw >> 6, h = gw & 63;

    float v0 = 0.f, v1 = 0.f;
    #pragma unroll
    for (int c = 0; c < NCHUNK; c++) {
        size_t o = (((size_t)c * BH + bn) * HDIM + h) * HDIM;
        v0 += g_scp[o + lane];
        v1 += g_scp[o + 32 + lane];
    }
    v0 *= (1.0f / 64.0f);   // 1/sqrt(4096)
    v1 *= (1.0f / 64.0f);

    float m = fmaxf(v0, v1);
    #pragma unroll
    for (int o = 16; o > 0; o >>= 1) m = fmaxf(m, __shfl_xor_sync(0xffffffffu, m, o));
    float e0 = __expf(v0 - m), e1 = __expf(v1 - m);
    float s = e0 + e1;
    #pragma unroll
    for (int o = 16; o > 0; o >>= 1) s += __shfl_xor_sync(0xffffffffu, s, o);
    float inv = 1.0f / s;

    size_t idx = ((size_t)bn * HDIM + h) * HDIM;
    g_attn[idx + lane] = e0 * inv;
    g_attn[idx + 32 + lane] = e1 * inv;
}

// ---------------- apply attention (tensor cores, RNA-rounded operands) ------
#define OPAD 68
__global__ __launch_bounds__(256)
void o_apply_tc_kernel()
{
    int bn = blockIdx.x;          // 0..63
    int st = blockIdx.y;          // 0..31 (128-token tile)
    int b = bn >> 4, n = bn & 15;

    __shared__ __align__(16) float sv[128 * OPAD];   // v tile  [s][k]
    __shared__ __align__(16) float sa[64 * OPAD];    // attn    [h][k]

    const float* gv = g_qkv + 2u * (size_t)TOK * EDIM;

    int tid = threadIdx.x;
    int wid = tid >> 5;
    int lane = tid & 31;
    int g = lane >> 2;
    int tig = lane & 3;

    size_t abase = (size_t)bn * HDIM * HDIM;
    #pragma unroll
    for (int rr = 0; rr < 4; rr++) {
        int f = tid + rr * 256;
        int h = f >> 4;
        int c4 = (f & 15) * 4;
        float4 t = *(const float4*)&g_attn[abase + h * HDIM + c4];
        t.x = to_tf32(t.x); t.y = to_tf32(t.y); t.z = to_tf32(t.z); t.w = to_tf32(t.w);
        *(float4*)&sa[h * OPAD + c4] = t;
    }
    size_t vbase = ((size_t)b * SEQ + (size_t)st * 128) * EDIM + n * HDIM;
    #pragma unroll
    for (int rr = 0; rr < 8; rr++) {
        int f = tid + rr * 256;
        int row = f >> 4;
        int c4 = (f & 15) * 4;
        float4 t = *(const float4*)&gv[vbase + (size_t)row * EDIM + c4];
        t.x = to_tf32(t.x); t.y = to_tf32(t.y); t.z = to_tf32(t.z); t.w = to_tf32(t.w);
        *(float4*)&sv[row * OPAD + c4] = t;
    }
    __syncthreads();

    int m0 = (wid & 3) * 32;
    int n0 = (wid >> 2) * 32;
    const uint32_t svb = smem_to_u32(sv);
    const uint32_t sab = smem_to_u32(sa);
    int q = lane >> 3, r = lane & 7;
    const uint32_t aBase = svb + (uint32_t)((m0 * OPAD + ((q & 1) * 8 + r) * OPAD + (q >> 1) * 4) * 4);
    const uint32_t bBase = sab + (uint32_t)((n0 * OPAD + ((q >> 1) * 8 + r) * OPAD + (q & 1) * 4) * 4);

    float acc[2][4][4];
    #pragma unroll
    for (int i = 0; i < 2; i++)
        #pragma unroll
        for (int j = 0; j < 4; j++)
            #pragma unroll
            for (int c = 0; c < 4; c++) acc[i][j][c] = 0.f;

    #pragma unroll
    for (int ks = 0; ks < 8; ks++) {
        uint32_t a[2][4];
        #pragma unroll
        for (int i = 0; i < 2; i++)
            ldsm_x4(a[i][0], a[i][1], a[i][2], a[i][3],
                    aBase + (uint32_t)(i * (16 * OPAD * 4) + ks * 32));
        uint32_t bfr[4][2];
        #pragma unroll
        for (int jp = 0; jp < 2; jp++)
            ldsm_x4(bfr[jp * 2][0], bfr[jp * 2][1], bfr[jp * 2 + 1][0], bfr[jp * 2 + 1][1],
                    bBase + (uint32_t)(jp * (16 * OPAD * 4) + ks * 32));
        #pragma unroll
        for (int i = 0; i < 2; i++)
            #pragma unroll
            for (int j = 0; j < 4; j++)
                mma_tf32(acc[i][j], a[i], bfr[j]);
    }

    size_t obase = ((size_t)b * SEQ + (size_t)st * 128) * EDIM + n * HDIM;
    #pragma unroll
    for (int i = 0; i < 2; i++) {
        int srow = m0 + 16 * i + g;
        #pragma unroll
        for (int j = 0; j < 4; j++) {
            int col = n0 + 8 * j + tig * 2;
            *(float2*)&g_o[obase + (size_t)srow * EDIM + col] =
                make_float2(acc[i][j][0], acc[i][j][1]);
            *(float2*)&g_o[obase + (size_t)(srow + 8) * EDIM + col] =
                make_float2(acc[i][j][2], acc[i][j][3]);
        }
    }
}

// ---------------- host launcher --------------------------------------------
extern "C" void kernel_launch(void* const* d_in, const int* in_sizes, int n_in,
                              void* d_out, int out_size)
{
    const float* query = (const float*)d_in[0];
    const float* gain  = (const float*)d_in[1];
    const float* wq    = (const float*)d_in[2];
    const float* wk    = (const float*)d_in[3];
    const float* wv    = (const float*)d_in[4];
    const float* wo    = (const float*)d_in[5];
    float* out = (float*)d_out;

    float *p_wn, *p_qkv, *p_o;
    cudaGetSymbolAddress((void**)&p_wn,  g_wn);
    cudaGetSymbolAddress((void**)&p_qkv, g_qkv);
    cudaGetSymbolAddress((void**)&p_o,   g_o);

    cudaFuncSetAttribute(gemm_tc_kernel,
                         cudaFuncAttributeMaxDynamicSharedMemorySize, GEMM_SMEM_BYTES);

    // 1) normalize weights (tf32-rounded)
    norm_weights_kernel<<<dim3(1024, 4), 256>>>(wq, wk, wv, wo, gain);

    // 2) fused Q/K/V projection (128x256 tiles, 512 threads)
    dim3 qkvgrid(3 * EDIM / 256, TOK / 128);   // (12, 128)
    gemm_tc_kernel<<<qkvgrid, 512, GEMM_SMEM_BYTES>>>(query, p_wn, p_qkv, nullptr, 1.0f);

    // 3) partial scores on tensor cores (q/k head-norm fused)
    scores_part_tc_kernel<<<dim3(BH, NCHUNK), 256>>>();

    // 4) reduce + softmax
    softmax_kernel<<<512, 256>>>();

    // 5) apply attention weights to v (tensor cores, RNA-rounded)
    o_apply_tc_kernel<<<dim3(BH, 32), 256>>>();

    // 6) output projection + residual mix: (res + proj) * sqrt(0.5)
    dim3 ogrid(EDIM / 256, TOK / 128);         // (4, 128)
    gemm_tc_kernel<<<ogrid, 512, GEMM_SMEM_BYTES>>>(p_o, p_wn + 3u * (1024u * 1024u), out, query, 0.70710678118654752f);
}

// round 14
// speedup vs baseline: 1.0746x; 1.0746x over previous
#include <cuda_runtime.h>
#include <cuda_bf16.h>
#include <cstdint>
#include <cmath>

// Problem constants: B=4, S=4096, E=1024, H=16, hd=64
#define TOK     16384            // B*S
#define EDIM    1024
#define NHEAD   16
#define HDIM    64
#define BH      64               // B*H
#define SEQ     4096
#define EPSN    1e-4f
#define NCHUNK  32               // s-chunks for partial scores

// ---------------- scratch (static device memory; no allocations) -----------
__device__ float g_wn[4u * 1024u * 1024u];                 // concat wq|wk|wv|wo (tf32)
__device__ float g_qkv[3u * (size_t)TOK * EDIM];           // q | k | v outputs
__device__ float g_o[(size_t)TOK * EDIM];                  // attn output (tf32-rounded)
__device__ float g_scp[(size_t)NCHUNK * BH * HDIM * HDIM]; // partial scores (32 MB)
__device__ float g_attn[BH * HDIM * HDIM];                 // softmaxed attn

// ======================= PTX helpers ========================================
__device__ __forceinline__ uint32_t smem_to_u32(const void* p) {
    uint32_t a;
    asm("{ .reg .u64 t; cvta.to.shared.u64 t, %1; cvt.u32.u64 %0, t; }" : "=r"(a) : "l"(p));
    return a;
}
__device__ __forceinline__ float to_tf32(float x) {
    float r;
    asm("cvt.rna.tf32.f32 %0, %1;" : "=f"(r) : "f"(x));
    return r;
}

#define CP_ASYNC16(dst, src) \
    asm volatile("cp.async.cg.shared.global [%0], [%1], 16;" :: "r"(dst), "l"(src))
#define CP_COMMIT()  asm volatile("cp.async.commit_group;" ::: "memory")
#define CP_WAIT0()   asm volatile("cp.async.wait_group 0;" ::: "memory")

// m16n8k8 tf32 MMA (arch-portable; lowers to fallback HMMA on sm_103)
__device__ __forceinline__ void mma_tf32(float* d, const uint32_t* a, const uint32_t* b) {
    asm volatile(
        "mma.sync.aligned.m16n8k8.row.col.f32.tf32.tf32.f32 "
        "{%0,%1,%2,%3}, {%4,%5,%6,%7}, {%8,%9}, {%0,%1,%2,%3};"
        : "+f"(d[0]), "+f"(d[1]), "+f"(d[2]), "+f"(d[3])
        : "r"(a[0]), "r"(a[1]), "r"(a[2]), "r"(a[3]), "r"(b[0]), "r"(b[1]));
}

// ldmatrix x4: four 8x8-b16 matrices == four 8x4-tf32 fragments
__device__ __forceinline__ void ldsm_x4(uint32_t& r0, uint32_t& r1, uint32_t& r2,
                                        uint32_t& r3, uint32_t addr) {
    asm volatile("ldmatrix.sync.aligned.m8n8.x4.shared.b16 {%0,%1,%2,%3}, [%4];"
                 : "=r"(r0), "=r"(r1), "=r"(r2), "=r"(r3) : "r"(addr));
}

// ======================= tf32 mma.sync GEMM =================================
// C[row, col_global] = sum_k A[row,k] * B[col_global,k]
// QKV fused: grid.x=24 routes 128-col tiles to q|k|v thirds; out: grid.x=8.
// CTA tile 64(M) x 128(N), 256 threads = 8 warps (2Mx4N, warp tile 32x32).
// K-chunk 32, 2-stage cp.async, one barrier per chunk, 3 CTAs/SM (24 warps).
#define PADW    36                        // floats per smem row (32 + 4 pad)
#define AROWS   64
#define BROWS   128
#define STAGEF  ((AROWS + BROWS) * PADW)  // 6912 floats per stage
#define GEMM_SMEM_BYTES (2 * STAGEF * 4)  // 55296 bytes

__global__ __launch_bounds__(256, 3)
void gemm_tc_kernel(const float* __restrict__ A, const float* __restrict__ B,
                    float* __restrict__ C, const float* __restrict__ Res, float alpha)
{
    extern __shared__ __align__(16) float smem[];
    const uint32_t sbase = smem_to_u32(smem);

    const int tid = threadIdx.x;
    const int wid = tid >> 5;
    const int lane = tid & 31;
    const int g = lane >> 2;            // group id 0..7
    const int tig = lane & 3;           // thread-in-group 0..3
    const int m0 = (wid >> 2) * 32;     // warp M offset (2 M-warps)
    const int n0 = (wid & 3) * 32;      // warp N offset (4 N-warps)
    const int bm = blockIdx.y * 64;
    const int bn = blockIdx.x * 128;    // global col base (may exceed 1024 in QKV mode)

    const int mat = bn >> 10;
    const int bnl = bn & 1023;          // col base within the output matrix
    float* Cbase = C + (size_t)mat * ((size_t)TOK * EDIM);

    // ldmatrix per-lane address offsets (in floats); q = lane>>3, r = lane&7
    const int q = lane >> 3, r = lane & 7;
    const int laneA = ((q & 1) * 8 + r) * PADW + (q >> 1) * 4;
    const int laneB = ((q >> 1) * 8 + r) * PADW + (q & 1) * 4;

    const char* gA = (const char*)(A + (size_t)bm * EDIM);
    const char* gB = (const char*)(B + (size_t)bn * EDIM);

    // loader: one K-chunk (A: 64 rows, B: 128 rows; 32 floats each) into stage st
    auto load_chunk = [&](int kc, int st) {
        uint32_t dA = sbase + (uint32_t)st * (STAGEF * 4);
        uint32_t dB = dA + AROWS * PADW * 4;
        int koff = kc * 128;                 // byte offset of chunk within row
        {   // A: 512 float4 slots (2 per thread)
            #pragma unroll
            for (int rr = 0; rr < 2; rr++) {
                int f = tid + rr * 256;
                int row = f >> 3;
                int seg = (f & 7) * 16;
                CP_ASYNC16(dA + (uint32_t)(row * (PADW * 4) + seg),
                           gA + (size_t)row * (EDIM * 4) + koff + seg);
            }
        }
        {   // B: 1024 float4 slots (4 per thread)
            #pragma unroll
            for (int rr = 0; rr < 4; rr++) {
                int f = tid + rr * 256;
                int row = f >> 3;
                int seg = (f & 7) * 16;
                CP_ASYNC16(dB + (uint32_t)(row * (PADW * 4) + seg),
                           gB + (size_t)row * (EDIM * 4) + koff + seg);
            }
        }
    };

    float acc[2][4][4];
    #pragma unroll
    for (int i = 0; i < 2; i++)
        #pragma unroll
        for (int j = 0; j < 4; j++)
            #pragma unroll
            for (int c = 0; c < 4; c++) acc[i][j][c] = 0.f;

    load_chunk(0, 0); CP_COMMIT();

    for (int c = 0; c < 32; c++) {
        CP_WAIT0();        // chunk c arrived (sole pending group)
        __syncthreads();   // all warps done computing chunk c-1 (stage (c+1)%2 free)

        if (c + 1 < 32) load_chunk(c + 1, (c + 1) & 1);
        CP_COMMIT();       // always commit (possibly empty group)

        const uint32_t stA = sbase + (uint32_t)(c & 1) * (STAGEF * 4);
        const uint32_t stB = stA + AROWS * PADW * 4;
        const uint32_t aBase = stA + (uint32_t)((m0 * PADW + laneA) * 4);
        const uint32_t bBase = stB + (uint32_t)((n0 * PADW + laneB) * 4);

        #pragma unroll
        for (int ks = 0; ks < 4; ks++) {
            uint32_t a[2][4];
            #pragma unroll
            for (int i = 0; i < 2; i++)
                ldsm_x4(a[i][0], a[i][1], a[i][2], a[i][3],
                        aBase + (uint32_t)(i * (16 * PADW * 4) + ks * 32));
            uint32_t b[4][2];
            #pragma unroll
            for (int jp = 0; jp < 2; jp++)
                ldsm_x4(b[jp * 2][0], b[jp * 2][1], b[jp * 2 + 1][0], b[jp * 2 + 1][1],
                        bBase + (uint32_t)(jp * (16 * PADW * 4) + ks * 32));
            #pragma unroll
            for (int i = 0; i < 2; i++)
                #pragma unroll
                for (int j = 0; j < 4; j++)
                    mma_tf32(acc[i][j], a[i], b[j]);
        }
    }

    // epilogue: c0,c1 -> (row, col..col+1); c2,c3 -> (row+8, ...)
    #pragma unroll
    for (int i = 0; i < 2; i++) {
        int row = bm + m0 + 16 * i + g;
        #pragma unroll
        for (int j = 0; j < 4; j++) {
            int col = bnl + n0 + 8 * j + tig * 2;
            float2 v0 = make_float2(acc[i][j][0], acc[i][j][1]);
            float2 v1 = make_float2(acc[i][j][2], acc[i][j][3]);
            if (Res != nullptr) {
                float2 r0 = *(const float2*)(Res + (size_t)row * EDIM + col);
                float2 r1 = *(const float2*)(Res + (size_t)(row + 8) * EDIM + col);
                v0.x = (v0.x + r0.x) * alpha; v0.y = (v0.y + r0.y) * alpha;
                v1.x = (v1.x + r1.x) * alpha; v1.y = (v1.y + r1.y) * alpha;
            }
            *(float2*)(Cbase + (size_t)row * EDIM + col) = v0;
            *(float2*)(Cbase + (size_t)(row + 8) * EDIM + col) = v1;
        }
    }
}

// ---------------- magnitude-preserving weight normalization (-> tf32) ------
__global__ __launch_bounds__(256)
void norm_weights_kernel(const float* __restrict__ wq, const float* __restrict__ wk,
                         const float* __restrict__ wv, const float* __restrict__ wo,
                         const float* __restrict__ gain_p)
{
    int row = blockIdx.x;
    int mat = blockIdx.y;
    const float* W = (mat == 0) ? wq : (mat == 1) ? wk : (mat == 2) ? wv : wo;
    const float* src = W + (size_t)row * EDIM;

    int tid = threadIdx.x;
    float4 w4 = *(const float4*)(src + tid * 4);
    float ss = w4.x * w4.x + w4.y * w4.y + w4.z * w4.z + w4.w * w4.w;

    __shared__ float red[8];
    int lane = tid & 31, warp = tid >> 5;
    #pragma unroll
    for (int o = 16; o > 0; o >>= 1) ss += __shfl_xor_sync(0xffffffffu, ss, o);
    if (lane == 0) red[warp] = ss;
    __syncthreads();
    if (tid == 0) {
        float t = 0.f;
        #pragma unroll
        for (int i = 0; i < 8; i++) t += red[i];
        red[0] = t;
    }
    __syncthreads();
    float scale = (*gain_p * (1.0f / 32.0f)) / (EPSN + sqrtf(red[0]) * (1.0f / 32.0f));

    float* dst = g_wn + (size_t)mat * (1024u * 1024u) + (size_t)row * EDIM + tid * 4;
    *(float4*)dst = make_float4(to_tf32(w4.x * scale), to_tf32(w4.y * scale),
                                to_tf32(w4.z * scale), to_tf32(w4.w * scale));
}

// ---------------- partial scores on tensor cores (+ fused q/k head-norm) ---
#define SPAD 36
__global__ __launch_bounds__(256)
void scores_part_tc_kernel()
{
    int bn = blockIdx.x;      // 0..63
    int chunk = blockIdx.y;   // 0..NCHUNK-1
    int b = bn >> 4, n = bn & 15;

    __shared__ __align__(16) float stq[64 * SPAD];   // q^T: [h][s], s-tile of 32
    __shared__ __align__(16) float stk[64 * SPAD];   // k^T: [k][s]

    const float* gq = g_qkv;
    const float* gk = g_qkv + (size_t)TOK * EDIM;

    int tid = threadIdx.x, wid = tid >> 5, lane = tid & 31;
    int g = lane >> 2, tig = lane & 3;

    int m0 = (wid & 3) * 16;
    int n0 = (wid >> 2) * 32;

    float acc[4][4];
    #pragma unroll
    for (int j = 0; j < 4; j++)
        #pragma unroll
        for (int c = 0; c < 4; c++) acc[j][c] = 0.f;

    const int CSZ = SEQ / NCHUNK;   // 128
    size_t tokbase = (size_t)b * SEQ + (size_t)chunk * CSZ;

    for (int s0 = 0; s0 < CSZ; s0 += 32) {
        #pragma unroll
        for (int rr = 0; rr < 4; rr++) {
            int srow = wid * 4 + rr;
            size_t goff = (tokbase + s0 + srow) * EDIM + (size_t)n * HDIM;
            float qa = gq[goff + lane], qb = gq[goff + 32 + lane];
            float ka = gk[goff + lane], kb = gk[goff + 32 + lane];
            float sq = qa * qa + qb * qb;
            float sk = ka * ka + kb * kb;
            #pragma unroll
            for (int o = 16; o > 0; o >>= 1) {
                sq += __shfl_xor_sync(0xffffffffu, sq, o);
                sk += __shfl_xor_sync(0xffffffffu, sk, o);
            }
            float iq = 1.0f / (EPSN + sqrtf(sq) * 0.125f);
            float ik = 1.0f / (EPSN + sqrtf(sk) * 0.125f);
            stq[lane * SPAD + srow]        = to_tf32(qa * iq);
            stq[(lane + 32) * SPAD + srow] = to_tf32(qb * iq);
            stk[lane * SPAD + srow]        = to_tf32(ka * ik);
            stk[(lane + 32) * SPAD + srow] = to_tf32(kb * ik);
        }
        __syncthreads();

        #pragma unroll
        for (int ks = 0; ks < 4; ks++) {
            int kc = ks * 8 + tig;
            uint32_t a[4];
            a[0] = __float_as_uint(stq[(m0 + g) * SPAD + kc]);
            a[1] = __float_as_uint(stq[(m0 + g + 8) * SPAD + kc]);
            a[2] = __float_as_uint(stq[(m0 + g) * SPAD + kc + 4]);
            a[3] = __float_as_uint(stq[(m0 + g + 8) * SPAD + kc + 4]);
            #pragma unroll
            for (int j = 0; j < 4; j++) {
                uint32_t bf[2];
                bf[0] = __float_as_uint(stk[(n0 + 8 * j + g) * SPAD + kc]);
                bf[1] = __float_as_uint(stk[(n0 + 8 * j + g) * SPAD + kc + 4]);
                mma_tf32(acc[j], a, bf);
            }
        }
        __syncthreads();
    }

    size_t base = ((size_t)chunk * BH + bn) * (HDIM * HDIM);
    #pragma unroll
    for (int j = 0; j < 4; j++) {
        int kcol = n0 + 8 * j + tig * 2;
        *(float2*)&g_scp[base + (size_t)(m0 + g) * HDIM + kcol] =
            make_float2(acc[j][0], acc[j][1]);
        *(float2*)&g_scp[base + (size_t)(m0 + g + 8) * HDIM + kcol] =
            make_float2(acc[j][2], acc[j][3]);
    }
}

// ---------------- softmax over k (rows of length 64) ------------------------
__global__ __launch_bounds__(256)
void softmax_kernel()
{
    int gw = blockIdx.x * 8 + (threadIdx.x >> 5);
    int lane = threadIdx.x & 31;
    int bn = gw >> 6, h = gw & 63;

    float v0 = 0.f, v1 = 0.f;
    #pragma unroll
    for (int c = 0; c < NCHUNK; c++) {
        size_t o = (((size_t)c * BH + bn) * HDIM + h) * HDIM;
        v0 += g_scp[o + lane];
        v1 += g_scp[o + 32 + lane];
    }
    v0 *= (1.0f / 64.0f);   // 1/sqrt(4096)
    v1 *= (1.0f / 64.0f);

    float m = fmaxf(v0, v1);
    #pragma unroll
    for (int o = 16; o > 0; o >>= 1) m = fmaxf(m, __shfl_xor_sync(0xffffffffu, m, o));
    float e0 = __expf(v0 - m), e1 = __expf(v1 - m);
    float s = e0 + e1;
    #pragma unroll
    for (int o = 16; o > 0; o >>= 1) s += __shfl_xor_sync(0xffffffffu, s, o);
    float inv = 1.0f / s;

    size_t idx = ((size_t)bn * HDIM + h) * HDIM;
    g_attn[idx + lane] = e0 * inv;
    g_attn[idx + 32 + lane] = e1 * inv;
}

// ---------------- apply attention (tensor cores, RNA-rounded operands) ------
#define OPAD 68
__global__ __launch_bounds__(256)
void o_apply_tc_kernel()
{
    int bn = blockIdx.x;          // 0..63
    int st = blockIdx.y;          // 0..31 (128-token tile)
    int b = bn >> 4, n = bn & 15;

    __shared__ __align__(16) float sv[128 * OPAD];   // v tile  [s][k]
    __shared__ __align__(16) float sa[64 * OPAD];    // attn    [h][k]

    const float* gv = g_qkv + 2u * (size_t)TOK * EDIM;

    int tid = threadIdx.x;
    int wid = tid >> 5;
    int lane = tid & 31;
    int g = lane >> 2;
    int tig = lane & 3;

    size_t abase = (size_t)bn * HDIM * HDIM;
    #pragma unroll
    for (int rr = 0; rr < 4; rr++) {
        int f = tid + rr * 256;
        int h = f >> 4;
        int c4 = (f & 15) * 4;
        float4 t = *(const float4*)&g_attn[abase + h * HDIM + c4];
        t.x = to_tf32(t.x); t.y = to_tf32(t.y); t.z = to_tf32(t.z); t.w = to_tf32(t.w);
        *(float4*)&sa[h * OPAD + c4] = t;
    }
    size_t vbase = ((size_t)b * SEQ + (size_t)st * 128) * EDIM + n * HDIM;
    #pragma unroll
    for (int rr = 0; rr < 8; rr++) {
        int f = tid + rr * 256;
        int row = f >> 4;
        int c4 = (f & 15) * 4;
        float4 t = *(const float4*)&gv[vbase + (size_t)row * EDIM + c4];
        t.x = to_tf32(t.x); t.y = to_tf32(t.y); t.z = to_tf32(t.z); t.w = to_tf32(t.w);
        *(float4*)&sv[row * OPAD + c4] = t;
    }
    __syncthreads();

    int m0 = (wid & 3) * 32;
    int n0 = (wid >> 2) * 32;
    const uint32_t svb = smem_to_u32(sv);
    const uint32_t sab = smem_to_u32(sa);
    int q = lane >> 3, r = lane & 7;
    const uint32_t aBase = svb + (uint32_t)((m0 * OPAD + ((q & 1) * 8 + r) * OPAD + (q >> 1) * 4) * 4);
    const uint32_t bBase = sab + (uint32_t)((n0 * OPAD + ((q >> 1) * 8 + r) * OPAD + (q & 1) * 4) * 4);

    float acc[2][4][4];
    #pragma unroll
    for (int i = 0; i < 2; i++)
        #pragma unroll
        for (int j = 0; j < 4; j++)
            #pragma unroll
            for (int c = 0; c < 4; c++) acc[i][j][c] = 0.f;

    #pragma unroll
    for (int ks = 0; ks < 8; ks++) {
        uint32_t a[2][4];
        #pragma unroll
        for (int i = 0; i < 2; i++)
            ldsm_x4(a[i][0], a[i][1], a[i][2], a[i][3],
                    aBase + (uint32_t)(i * (16 * OPAD * 4) + ks * 32));
        uint32_t bfr[4][2];
        #pragma unroll
        for (int jp = 0; jp < 2; jp++)
            ldsm_x4(bfr[jp * 2][0], bfr[jp * 2][1], bfr[jp * 2 + 1][0], bfr[jp * 2 + 1][1],
                    bBase + (uint32_t)(jp * (16 * OPAD * 4) + ks * 32));
        #pragma unroll
        for (int i = 0; i < 2; i++)
            #pragma unroll
            for (int j = 0; j < 4; j++)
                mma_tf32(acc[i][j], a[i], bfr[j]);
    }

    // RNA-round outputs: the out-projection GEMM truncates its A operand (RZ);
    // rounding here removes the truncation bias.
    size_t obase = ((size_t)b * SEQ + (size_t)st * 128) * EDIM + n * HDIM;
    #pragma unroll
    for (int i = 0; i < 2; i++) {
        int srow = m0 + 16 * i + g;
        #pragma unroll
        for (int j = 0; j < 4; j++) {
            int col = n0 + 8 * j + tig * 2;
            *(float2*)&g_o[obase + (size_t)srow * EDIM + col] =
                make_float2(to_tf32(acc[i][j][0]), to_tf32(acc[i][j][1]));
            *(float2*)&g_o[obase + (size_t)(srow + 8) * EDIM + col] =
                make_float2(to_tf32(acc[i][j][2]), to_tf32(acc[i][j][3]));
        }
    }
}

// ---------------- host launcher --------------------------------------------
extern "C" void kernel_launch(void* const* d_in, const int* in_sizes, int n_in,
                              void* d_out, int out_size)
{
    const float* query = (const float*)d_in[0];
    const float* gain  = (const float*)d_in[1];
    const float* wq    = (const float*)d_in[2];
    const float* wk    = (const float*)d_in[3];
    const float* wv    = (const float*)d_in[4];
    const float* wo    = (const float*)d_in[5];
    float* out = (float*)d_out;

    float *p_wn, *p_qkv, *p_o;
    cudaGetSymbolAddress((void**)&p_wn,  g_wn);
    cudaGetSymbolAddress((void**)&p_qkv, g_qkv);
    cudaGetSymbolAddress((void**)&p_o,   g_o);

    cudaFuncSetAttribute(gemm_tc_kernel,
                         cudaFuncAttributeMaxDynamicSharedMemorySize, GEMM_SMEM_BYTES);

    // 1) normalize weights (tf32-rounded)
    norm_weights_kernel<<<dim3(1024, 4), 256>>>(wq, wk, wv, wo, gain);

    // 2) fused Q/K/V projection (64x128 tiles, 3 CTAs/SM)
    dim3 qkvgrid(3 * EDIM / 128, TOK / 64);    // (24, 256)
    gemm_tc_kernel<<<qkvgrid, 256, GEMM_SMEM_BYTES>>>(query, p_wn, p_qkv, nullptr, 1.0f);

    // 3) partial scores on tensor cores (q/k head-norm fused)
    scores_part_tc_kernel<<<dim3(BH, NCHUNK), 256>>>();

    // 4) reduce + softmax
    softmax_kernel<<<512, 256>>>();

    // 5) apply attention weights to v (tensor cores, RNA-rounded)
    o_apply_tc_kernel<<<dim3(BH, 32), 256>>>();

    // 6) output projection + residual mix: (res + proj) * sqrt(0.5)
    dim3 ogrid(EDIM / 128, TOK / 64);          // (8, 256)
    gemm_tc_kernel<<<ogrid, 256, GEMM_SMEM_BYTES>>>(p_o, p_wn + 3u * (1024u * 1024u), out, query, 0.70710678118654752f);
}

// round 15
// speedup vs baseline: 1.1626x; 1.0820x over previous
#include <cuda_runtime.h>
#include <cuda_bf16.h>
#include <cstdint>
#include <cmath>

// Problem constants: B=4, S=4096, E=1024, H=16, hd=64
#define TOK     16384            // B*S
#define EDIM    1024
#define NHEAD   16
#define HDIM    64
#define BH      64               // B*H
#define SEQ     4096
#define EPSN    1e-4f
#define NCHUNK  16               // s-chunks for partial scores

// ---------------- scratch (static device memory; no allocations) -----------
__device__ float g_wn[4u * 1024u * 1024u];                 // concat wq|wk|wv|wo (tf32)
__device__ float g_qkv[3u * (size_t)TOK * EDIM];           // q | k | v outputs
__device__ float g_o[(size_t)TOK * EDIM];                  // attn output (tf32-rounded)
__device__ float g_scp[(size_t)NCHUNK * BH * HDIM * HDIM]; // partial scores (16 MB)
__device__ float g_attn[BH * HDIM * HDIM];                 // softmaxed attn

// ======================= PTX helpers ========================================
__device__ __forceinline__ uint32_t smem_to_u32(const void* p) {
    uint32_t a;
    asm("{ .reg .u64 t; cvta.to.shared.u64 t, %1; cvt.u32.u64 %0, t; }" : "=r"(a) : "l"(p));
    return a;
}
__device__ __forceinline__ float to_tf32(float x) {
    float r;
    asm("cvt.rna.tf32.f32 %0, %1;" : "=f"(r) : "f"(x));
    return r;
}

#define CP_ASYNC16(dst, src) \
    asm volatile("cp.async.cg.shared.global [%0], [%1], 16;" :: "r"(dst), "l"(src))
#define CP_COMMIT()  asm volatile("cp.async.commit_group;" ::: "memory")
#define CP_WAIT1()   asm volatile("cp.async.wait_group 1;" ::: "memory")

// m16n8k8 tf32 MMA (arch-portable; lowers to fallback HMMA on sm_103)
__device__ __forceinline__ void mma_tf32(float* d, const uint32_t* a, const uint32_t* b) {
    asm volatile(
        "mma.sync.aligned.m16n8k8.row.col.f32.tf32.tf32.f32 "
        "{%0,%1,%2,%3}, {%4,%5,%6,%7}, {%8,%9}, {%0,%1,%2,%3};"
        : "+f"(d[0]), "+f"(d[1]), "+f"(d[2]), "+f"(d[3])
        : "r"(a[0]), "r"(a[1]), "r"(a[2]), "r"(a[3]), "r"(b[0]), "r"(b[1]));
}

// ldmatrix x4: four 8x8-b16 matrices == four 8x4-tf32 fragments
__device__ __forceinline__ void ldsm_x4(uint32_t& r0, uint32_t& r1, uint32_t& r2,
                                        uint32_t& r3, uint32_t addr) {
    asm volatile("ldmatrix.sync.aligned.m8n8.x4.shared.b16 {%0,%1,%2,%3}, [%4];"
                 : "=r"(r0), "=r"(r1), "=r"(r2), "=r"(r3) : "r"(addr));
}

// ======================= tf32 mma.sync GEMM (R12 best-known config) =========
// C[row, col_global] = sum_k A[row,k] * B[col_global,k]
// QKV fused: grid.x=24 routes cols to q|k|v thirds; others: grid.x=8, mat=0.
// 128x128 CTA tile, K-chunk 32, 3-stage cp.async, one barrier per chunk,
// 2 CTAs/SM (16 warps). 8 warps = 2(M)x4(N); warp tile 64x32.
#define PADW   36                       // floats per smem row (32 + 4 pad)
#define STAGEF (128 * PADW)             // 4608 floats per matrix per stage
#define GEMM_SMEM_BYTES (6 * STAGEF * 4)  // A:3 + B:3 stages = 110592

__global__ __launch_bounds__(256, 2)
void gemm_tc_kernel(const float* __restrict__ A, const float* __restrict__ B,
                    float* __restrict__ C, const float* __restrict__ Res, float alpha)
{
    extern __shared__ __align__(16) float smem[];
    float* sA0 = smem;                  // 3 stages of A
    float* sB0 = smem + 3 * STAGEF;     // 3 stages of B
    const uint32_t sbaseA = smem_to_u32(sA0);
    const uint32_t sbaseB = smem_to_u32(sB0);

    const int tid = threadIdx.x;
    const int wid = tid >> 5;
    const int lane = tid & 31;
    const int g = lane >> 2;            // group id 0..7
    const int tig = lane & 3;           // thread-in-group 0..3
    const int m0 = (wid >> 2) * 64;     // warp M offset in tile
    const int n0 = (wid & 3) * 32;      // warp N offset in tile
    const int bm = blockIdx.y * 128;
    const int bn = blockIdx.x * 128;    // global col base (may exceed 1024 in QKV mode)

    const int mat = bn >> 10;
    const int bnl = bn & 1023;          // col base within the output matrix
    float* Cbase = C + (size_t)mat * ((size_t)TOK * EDIM);

    const int q = lane >> 3, r = lane & 7;
    const int laneA = ((q & 1) * 8 + r) * PADW + (q >> 1) * 4;
    const int laneB = ((q >> 1) * 8 + r) * PADW + (q & 1) * 4;

    const char* gA = (const char*)(A + (size_t)bm * EDIM);
    const char* gB = (const char*)(B + (size_t)bn * EDIM);

    auto load_chunk = [&](int kc, int st) {
        uint32_t dA = sbaseA + (uint32_t)st * (STAGEF * 4);
        uint32_t dB = sbaseB + (uint32_t)st * (STAGEF * 4);
        int koff = kc * 128;                 // byte offset of chunk within row
        #pragma unroll
        for (int rr = 0; rr < 4; rr++) {
            int f = tid + rr * 256;          // 0..1023 float4 slots
            int row = f >> 3;                // 0..127
            int seg = (f & 7) * 16;          // byte seg within chunk row
            uint32_t so = (uint32_t)(row * (PADW * 4) + seg);
            size_t  go = (size_t)row * (EDIM * 4) + koff + seg;
            CP_ASYNC16(dA + so, gA + go);
            CP_ASYNC16(dB + so, gB + go);
        }
    };

    float acc[4][4][4];
    #pragma unroll
    for (int i = 0; i < 4; i++)
        #pragma unroll
        for (int j = 0; j < 4; j++)
            #pragma unroll
            for (int c = 0; c < 4; c++) acc[i][j][c] = 0.f;

    load_chunk(0, 0); CP_COMMIT();
    load_chunk(1, 1); CP_COMMIT();

    for (int c = 0; c < 32; c++) {
        CP_WAIT1();        // pending {c, c+1} -> wait for chunk c
        __syncthreads();   // chunk c visible; all warps done reading stage (c-1)%3

        if (c + 2 < 32) load_chunk(c + 2, (c + 2) % 3);
        CP_COMMIT();                      // always commit (possibly empty group)

        const uint32_t stA = sbaseA + (uint32_t)(c % 3) * (STAGEF * 4);
        const uint32_t stB = sbaseB + (uint32_t)(c % 3) * (STAGEF * 4);
        const uint32_t aBase = stA + (uint32_t)((m0 * PADW + laneA) * 4);
        const uint32_t bBase = stB + (uint32_t)((n0 * PADW + laneB) * 4);

        #pragma unroll
        for (int ks = 0; ks < 4; ks++) {
            uint32_t a[4][4];
            #pragma unroll
            for (int i = 0; i < 4; i++)
                ldsm_x4(a[i][0], a[i][1], a[i][2], a[i][3],
                        aBase + (uint32_t)(i * (16 * PADW * 4) + ks * 32));
            uint32_t b[4][2];
            #pragma unroll
            for (int jp = 0; jp < 2; jp++)
                ldsm_x4(b[jp * 2][0], b[jp * 2][1], b[jp * 2 + 1][0], b[jp * 2 + 1][1],
                        bBase + (uint32_t)(jp * (16 * PADW * 4) + ks * 32));
            #pragma unroll
            for (int i = 0; i < 4; i++)
                #pragma unroll
                for (int j = 0; j < 4; j++)
                    mma_tf32(acc[i][j], a[i], b[j]);
        }
    }

    #pragma unroll
    for (int i = 0; i < 4; i++) {
        int row = bm + m0 + 16 * i + g;
        #pragma unroll
        for (int j = 0; j < 4; j++) {
            int col = bnl + n0 + 8 * j + tig * 2;
            float2 v0 = make_float2(acc[i][j][0], acc[i][j][1]);
            float2 v1 = make_float2(acc[i][j][2], acc[i][j][3]);
            if (Res != nullptr) {
                float2 r0 = *(const float2*)(Res + (size_t)row * EDIM + col);
                float2 r1 = *(const float2*)(Res + (size_t)(row + 8) * EDIM + col);
                v0.x = (v0.x + r0.x) * alpha; v0.y = (v0.y + r0.y) * alpha;
                v1.x = (v1.x + r1.x) * alpha; v1.y = (v1.y + r1.y) * alpha;
            }
            *(float2*)(Cbase + (size_t)row * EDIM + col) = v0;
            *(float2*)(Cbase + (size_t)(row + 8) * EDIM + col) = v1;
        }
    }
}

// ---------------- magnitude-preserving weight normalization (-> tf32) ------
__global__ __launch_bounds__(256)
void norm_weights_kernel(const float* __restrict__ wq, const float* __restrict__ wk,
                         const float* __restrict__ wv, const float* __restrict__ wo,
                         const float* __restrict__ gain_p)
{
    int row = blockIdx.x;
    int mat = blockIdx.y;
    const float* W = (mat == 0) ? wq : (mat == 1) ? wk : (mat == 2) ? wv : wo;
    const float* src = W + (size_t)row * EDIM;

    int tid = threadIdx.x;
    float4 w4 = *(const float4*)(src + tid * 4);
    float ss = w4.x * w4.x + w4.y * w4.y + w4.z * w4.z + w4.w * w4.w;

    __shared__ float red[8];
    int lane = tid & 31, warp = tid >> 5;
    #pragma unroll
    for (int o = 16; o > 0; o >>= 1) ss += __shfl_xor_sync(0xffffffffu, ss, o);
    if (lane == 0) red[warp] = ss;
    __syncthreads();
    if (tid == 0) {
        float t = 0.f;
        #pragma unroll
        for (int i = 0; i < 8; i++) t += red[i];
        red[0] = t;
    }
    __syncthreads();
    float scale = (*gain_p * (1.0f / 32.0f)) / (EPSN + sqrtf(red[0]) * (1.0f / 32.0f));

    float* dst = g_wn + (size_t)mat * (1024u * 1024u) + (size_t)row * EDIM + tid * 4;
    *(float4*)dst = make_float4(to_tf32(w4.x * scale), to_tf32(w4.y * scale),
                                to_tf32(w4.z * scale), to_tf32(w4.w * scale));
}

// ---------------- partial scores on tensor cores (+ fused q/k head-norm) ---
#define SPAD 36
__global__ __launch_bounds__(256)
void scores_part_tc_kernel()
{
    int bn = blockIdx.x;      // 0..63
    int chunk = blockIdx.y;   // 0..NCHUNK-1
    int b = bn >> 4, n = bn & 15;

    __shared__ __align__(16) float stq[64 * SPAD];   // q^T: [h][s], s-tile of 32
    __shared__ __align__(16) float stk[64 * SPAD];   // k^T: [k][s]

    const float* gq = g_qkv;
    const float* gk = g_qkv + (size_t)TOK * EDIM;

    int tid = threadIdx.x, wid = tid >> 5, lane = tid & 31;
    int g = lane >> 2, tig = lane & 3;

    int m0 = (wid & 3) * 16;
    int n0 = (wid >> 2) * 32;

    float acc[4][4];
    #pragma unroll
    for (int j = 0; j < 4; j++)
        #pragma unroll
        for (int c = 0; c < 4; c++) acc[j][c] = 0.f;

    const int CSZ = SEQ / NCHUNK;   // 256
    size_t tokbase = (size_t)b * SEQ + (size_t)chunk * CSZ;

    for (int s0 = 0; s0 < CSZ; s0 += 32) {
        #pragma unroll
        for (int rr = 0; rr < 4; rr++) {
            int srow = wid * 4 + rr;
            size_t goff = (tokbase + s0 + srow) * EDIM + (size_t)n * HDIM;
            float qa = gq[goff + lane], qb = gq[goff + 32 + lane];
            float ka = gk[goff + lane], kb = gk[goff + 32 + lane];
            float sq = qa * qa + qb * qb;
            float sk = ka * ka + kb * kb;
            #pragma unroll
            for (int o = 16; o > 0; o >>= 1) {
                sq += __shfl_xor_sync(0xffffffffu, sq, o);
                sk += __shfl_xor_sync(0xffffffffu, sk, o);
            }
            float iq = 1.0f / (EPSN + sqrtf(sq) * 0.125f);
            float ik = 1.0f / (EPSN + sqrtf(sk) * 0.125f);
            stq[lane * SPAD + srow]        = to_tf32(qa * iq);
            stq[(lane + 32) * SPAD + srow] = to_tf32(qb * iq);
            stk[lane * SPAD + srow]        = to_tf32(ka * ik);
            stk[(lane + 32) * SPAD + srow] = to_tf32(kb * ik);
        }
        __syncthreads();

        #pragma unroll
        for (int ks = 0; ks < 4; ks++) {
            int kc = ks * 8 + tig;
            uint32_t a[4];
            a[0] = __float_as_uint(stq[(m0 + g) * SPAD + kc]);
            a[1] = __float_as_uint(stq[(m0 + g + 8) * SPAD + kc]);
            a[2] = __float_as_uint(stq[(m0 + g) * SPAD + kc + 4]);
            a[3] = __float_as_uint(stq[(m0 + g + 8) * SPAD + kc + 4]);
            #pragma unroll
            for (int j = 0; j < 4; j++) {
                uint32_t bf[2];
                bf[0] = __float_as_uint(stk[(n0 + 8 * j + g) * SPAD + kc]);
                bf[1] = __float_as_uint(stk[(n0 + 8 * j + g) * SPAD + kc + 4]);
                mma_tf32(acc[j], a, bf);
            }
        }
        __syncthreads();
    }

    size_t base = ((size_t)chunk * BH + bn) * (HDIM * HDIM);
    #pragma unroll
    for (int j = 0; j < 4; j++) {
        int kcol = n0 + 8 * j + tig * 2;
        *(float2*)&g_scp[base + (size_t)(m0 + g) * HDIM + kcol] =
            make_float2(acc[j][0], acc[j][1]);
        *(float2*)&g_scp[base + (size_t)(m0 + g + 8) * HDIM + kcol] =
            make_float2(acc[j][2], acc[j][3]);
    }
}

// ---------------- softmax over k (rows of length 64) ------------------------
__global__ __launch_bounds__(256)
void softmax_kernel()
{
    int gw = blockIdx.x * 8 + (threadIdx.x >> 5);
    int lane = threadIdx.x & 31;
    int bn = gw >> 6, h = gw & 63;

    float v0 = 0.f, v1 = 0.f;
    #pragma unroll
    for (int c = 0; c < NCHUNK; c++) {
        size_t o = (((size_t)c * BH + bn) * HDIM + h) * HDIM;
        v0 += g_scp[o + lane];
        v1 += g_scp[o + 32 + lane];
    }
    v0 *= (1.0f / 64.0f);   // 1/sqrt(4096)
    v1 *= (1.0f / 64.0f);

    float m = fmaxf(v0, v1);
    #pragma unroll
    for (int o = 16; o > 0; o >>= 1) m = fmaxf(m, __shfl_xor_sync(0xffffffffu, m, o));
    float e0 = __expf(v0 - m), e1 = __expf(v1 - m);
    float s = e0 + e1;
    #pragma unroll
    for (int o = 16; o > 0; o >>= 1) s += __shfl_xor_sync(0xffffffffu, s, o);
    float inv = 1.0f / s;

    size_t idx = ((size_t)bn * HDIM + h) * HDIM;
    g_attn[idx + lane] = e0 * inv;
    g_attn[idx + 32 + lane] = e1 * inv;
}

// ---------------- apply attention (tensor cores, RNA-rounded operands) ------
#define OPAD 68
__global__ __launch_bounds__(256)
void o_apply_tc_kernel()
{
    int bn = blockIdx.x;          // 0..63
    int st = blockIdx.y;          // 0..31 (128-token tile)
    int b = bn >> 4, n = bn & 15;

    __shared__ __align__(16) float sv[128 * OPAD];   // v tile  [s][k]
    __shared__ __align__(16) float sa[64 * OPAD];    // attn    [h][k]

    const float* gv = g_qkv + 2u * (size_t)TOK * EDIM;

    int tid = threadIdx.x;
    int wid = tid >> 5;
    int lane = tid & 31;
    int g = lane >> 2;
    int tig = lane & 3;

    size_t abase = (size_t)bn * HDIM * HDIM;
    #pragma unroll
    for (int rr = 0; rr < 4; rr++) {
        int f = tid + rr * 256;
        int h = f >> 4;
        int c4 = (f & 15) * 4;
        float4 t = *(const float4*)&g_attn[abase + h * HDIM + c4];
        t.x = to_tf32(t.x); t.y = to_tf32(t.y); t.z = to_tf32(t.z); t.w = to_tf32(t.w);
        *(float4*)&sa[h * OPAD + c4] = t;
    }
    size_t vbase = ((size_t)b * SEQ + (size_t)st * 128) * EDIM + n * HDIM;
    #pragma unroll
    for (int rr = 0; rr < 8; rr++) {
        int f = tid + rr * 256;
        int row = f >> 4;
        int c4 = (f & 15) * 4;
        float4 t = *(const float4*)&gv[vbase + (size_t)row * EDIM + c4];
        t.x = to_tf32(t.x); t.y = to_tf32(t.y); t.z = to_tf32(t.z); t.w = to_tf32(t.w);
        *(float4*)&sv[row * OPAD + c4] = t;
    }
    __syncthreads();

    int m0 = (wid & 3) * 32;
    int n0 = (wid >> 2) * 32;
    const uint32_t svb = smem_to_u32(sv);
    const uint32_t sab = smem_to_u32(sa);
    int q = lane >> 3, r = lane & 7;
    const uint32_t aBase = svb + (uint32_t)((m0 * OPAD + ((q & 1) * 8 + r) * OPAD + (q >> 1) * 4) * 4);
    const uint32_t bBase = sab + (uint32_t)((n0 * OPAD + ((q >> 1) * 8 + r) * OPAD + (q & 1) * 4) * 4);

    float acc[2][4][4];
    #pragma unroll
    for (int i = 0; i < 2; i++)
        #pragma unroll
        for (int j = 0; j < 4; j++)
            #pragma unroll
            for (int c = 0; c < 4; c++) acc[i][j][c] = 0.f;

    #pragma unroll
    for (int ks = 0; ks < 8; ks++) {
        uint32_t a[2][4];
        #pragma unroll
        for (int i = 0; i < 2; i++)
            ldsm_x4(a[i][0], a[i][1], a[i][2], a[i][3],
                    aBase + (uint32_t)(i * (16 * OPAD * 4) + ks * 32));
        uint32_t bfr[4][2];
        #pragma unroll
        for (int jp = 0; jp < 2; jp++)
            ldsm_x4(bfr[jp * 2][0], bfr[jp * 2][1], bfr[jp * 2 + 1][0], bfr[jp * 2 + 1][1],
                    bBase + (uint32_t)(jp * (16 * OPAD * 4) + ks * 32));
        #pragma unroll
        for (int i = 0; i < 2; i++)
            #pragma unroll
            for (int j = 0; j < 4; j++)
                mma_tf32(acc[i][j], a[i], bfr[j]);
    }

    // RNA-round outputs: removes RZ truncation bias in the out-projection GEMM
    size_t obase = ((size_t)b * SEQ + (size_t)st * 128) * EDIM + n * HDIM;
    #pragma unroll
    for (int i = 0; i < 2; i++) {
        int srow = m0 + 16 * i + g;
        #pragma unroll
        for (int j = 0; j < 4; j++) {
            int col = n0 + 8 * j + tig * 2;
            *(float2*)&g_o[obase + (size_t)srow * EDIM + col] =
                make_float2(to_tf32(acc[i][j][0]), to_tf32(acc[i][j][1]));
            *(float2*)&g_o[obase + (size_t)(srow + 8) * EDIM + col] =
                make_float2(to_tf32(acc[i][j][2]), to_tf32(acc[i][j][3]));
        }
    }
}

// ---------------- host launcher --------------------------------------------
extern "C" void kernel_launch(void* const* d_in, const int* in_sizes, int n_in,
                              void* d_out, int out_size)
{
    const float* query = (const float*)d_in[0];
    const float* gain  = (const float*)d_in[1];
    const float* wq    = (const float*)d_in[2];
    const float* wk    = (const float*)d_in[3];
    const float* wv    = (const float*)d_in[4];
    const float* wo    = (const float*)d_in[5];
    float* out = (float*)d_out;

    float *p_wn, *p_qkv, *p_o;
    cudaGetSymbolAddress((void**)&p_wn,  g_wn);
    cudaGetSymbolAddress((void**)&p_qkv, g_qkv);
    cudaGetSymbolAddress((void**)&p_o,   g_o);

    cudaFuncSetAttribute(gemm_tc_kernel,
                         cudaFuncAttributeMaxDynamicSharedMemorySize, GEMM_SMEM_BYTES);

    // 1) normalize weights (tf32-rounded)
    norm_weights_kernel<<<dim3(1024, 4), 256>>>(wq, wk, wv, wo, gain);

    // 2) fused Q/K/V projection (128x128 tiles, 2 CTAs/SM — best-known config)
    dim3 qkvgrid(3 * EDIM / 128, TOK / 128);   // (24, 128)
    gemm_tc_kernel<<<qkvgrid, 256, GEMM_SMEM_BYTES>>>(query, p_wn, p_qkv, nullptr, 1.0f);

    // 3) partial scores on tensor cores (q/k head-norm fused)
    scores_part_tc_kernel<<<dim3(BH, NCHUNK), 256>>>();

    // 4) reduce + softmax
    softmax_kernel<<<512, 256>>>();

    // 5) apply attention weights to v (tensor cores, RNA-rounded both ways)
    o_apply_tc_kernel<<<dim3(BH, 32), 256>>>();

    // 6) output projection + residual mix: (res + proj) * sqrt(0.5)
    dim3 ogrid(EDIM / 128, TOK / 128);         // (8, 128)
    gemm_tc_kernel<<<ogrid, 256, GEMM_SMEM_BYTES>>>(p_o, p_wn + 3u * (1024u * 1024u), out, query, 0.70710678118654752f);
}